// round 7
// baseline (speedup 1.0000x reference)
#include <cuda_runtime.h>
#include <cuda_fp16.h>
#include <cstdint>
#include <math.h>

#define S_LEN   2048
#define DHEAD   128
#define NHEADS  64        // B*H = 4*16
#define BM      128
#define BN      64
#define THREADS 128       // 4 warps, 32 Q-rows each

// smem: swizzled 256B rows, no padding
#define SM_QHI  0
#define SM_QLO  32768
#define SM_KHI  65536
#define SM_KLO  81920
#define SM_V    98304
#define SM_TOT  114688

// (1/0.32) * log2(e), folded into Q at load
#define SFACT   4.5084219932497354f

// swizzled byte offset: row (256B each), ch = 16B chunk index 0..15
#define SWZ(row, ch) ((uint32_t)(row) * 256u + (uint32_t)((((ch) ^ ((row) & 7)) << 4)))

static __device__ __forceinline__ float ex2f(float x) {
    float r; asm("ex2.approx.f32 %0, %1;" : "=f"(r) : "f"(x)); return r;
}
static __device__ __forceinline__ uint32_t pack_h2(float a, float b) {
    __half2 h = __floats2half2_rn(a, b);
    return *reinterpret_cast<uint32_t*>(&h);
}
static __device__ __forceinline__ void ldsm4(uint32_t* r, uint32_t a) {
    asm volatile("ldmatrix.sync.aligned.m8n8.x4.shared.b16 {%0,%1,%2,%3}, [%4];"
                 : "=r"(r[0]), "=r"(r[1]), "=r"(r[2]), "=r"(r[3]) : "r"(a));
}
static __device__ __forceinline__ void ldsm4t(uint32_t* r, uint32_t a) {
    asm volatile("ldmatrix.sync.aligned.m8n8.x4.trans.shared.b16 {%0,%1,%2,%3}, [%4];"
                 : "=r"(r[0]), "=r"(r[1]), "=r"(r[2]), "=r"(r[3]) : "r"(a));
}
static __device__ __forceinline__ void mma_f16(float* d, const uint32_t* a, const uint32_t* b) {
    asm volatile(
        "mma.sync.aligned.m16n8k16.row.col.f32.f16.f16.f32 "
        "{%0,%1,%2,%3}, {%4,%5,%6,%7}, {%8,%9}, {%0,%1,%2,%3};\n"
        : "+f"(d[0]), "+f"(d[1]), "+f"(d[2]), "+f"(d[3])
        : "r"(a[0]), "r"(a[1]), "r"(a[2]), "r"(a[3]), "r"(b[0]), "r"(b[1]));
}
// split 8 consecutive floats into hi/lo fp16 planes (packed half2 x4)
static __device__ __forceinline__ void split8(const float* x, uint4& uh, uint4& ul) {
    uint32_t h[4], l[4];
    #pragma unroll
    for (int j = 0; j < 4; ++j) {
        float a = x[2 * j], b = x[2 * j + 1];
        __half ha = __float2half_rn(a), hb = __float2half_rn(b);
        h[j] = pack_h2(__half2float(ha), __half2float(hb));
        l[j] = pack_h2(a - __half2float(ha), b - __half2float(hb));
    }
    uh = make_uint4(h[0], h[1], h[2], h[3]);
    ul = make_uint4(l[0], l[1], l[2], l[3]);
}
static __device__ __forceinline__ uint4 pack8(const float* x) {
    return make_uint4(pack_h2(x[0], x[1]), pack_h2(x[2], x[3]),
                      pack_h2(x[4], x[5]), pack_h2(x[6], x[7]));
}

__global__ __launch_bounds__(THREADS, 2)
void fa_w32_kernel(const float* __restrict__ Q, const float* __restrict__ K,
                   const float* __restrict__ V, float* __restrict__ O) {
    extern __shared__ __align__(16) char sm[];
    const uint32_t smb = (uint32_t)__cvta_generic_to_shared(sm);

    const int tid  = threadIdx.x;
    const int warp = tid >> 5;
    const int lane = tid & 31;
    const int g    = lane >> 2;
    const int c    = lane & 3;
    const uint32_t rl = lane & 7;   // swizzle row-low bits (invariant for all frag rows)

    const int bh = blockIdx.y;
    const int q0 = blockIdx.x * BM;
    const size_t head = (size_t)bh * S_LEN * DHEAD;
    const int rbase = warp * 32;    // 32 rows per warp (2 m16 tiles)

    // ---- load Q tile: scale, split hi/lo fp16, swizzled store ----
    for (int i = tid; i < BM * 16; i += THREADS) {
        int row = i >> 4, ch = i & 15;
        const float* src = Q + head + (size_t)(q0 + row) * DHEAD + ch * 8;
        float4 f0 = *(const float4*)src;
        float4 f1 = *(const float4*)(src + 4);
        float f[8] = {f0.x*SFACT, f0.y*SFACT, f0.z*SFACT, f0.w*SFACT,
                      f1.x*SFACT, f1.y*SFACT, f1.z*SFACT, f1.w*SFACT};
        uint4 uh, ul; split8(f, uh, ul);
        uint32_t off = SWZ(row, ch);
        *(uint4*)(sm + SM_QHI + off) = uh;
        *(uint4*)(sm + SM_QLO + off) = ul;
    }

    // ---- per-lane fragment base addresses ----
    // A (Q): mt rows rbase + mt*16 + (lane&15); chunk0 = lane>>4
    const uint32_t qrow0 = (uint32_t)(rbase + (lane & 15)) * 256u;
    const uint32_t qA_h0 = smb + SM_QHI + qrow0;
    const uint32_t qA_l0 = smb + SM_QLO + qrow0;
    const uint32_t chA0 = lane >> 4;
    // B (K): row = (lane&7) + 8*(lane>>4) [+16*]; chunk0 = (lane>>3)&1
    const uint32_t krow = (uint32_t)((lane & 7) + ((lane >> 4) << 3)) * 256u;
    const uint32_t kB_h = smb + SM_KHI + krow;
    const uint32_t kB_l = smb + SM_KLO + krow;
    const uint32_t chB0 = (lane >> 3) & 1;
    // B (V, trans): row = (lane&7) + 8*((lane>>3)&1) [+16*k2]; chunk0 = lane>>4
    const uint32_t vrow = (uint32_t)((lane & 7) + (((lane >> 3) & 1) << 3)) * 256u;
    const uint32_t vB   = smb + SM_V + vrow;
    const uint32_t chV0 = lane >> 4;

    float o[2][16][4];
    #pragma unroll
    for (int mt = 0; mt < 2; ++mt)
        #pragma unroll
        for (int i = 0; i < 16; i++) {
            o[mt][i][0]=0.f; o[mt][i][1]=0.f; o[mt][i][2]=0.f; o[mt][i][3]=0.f;
        }
    float mrun[2][2] = {{-INFINITY,-INFINITY},{-INFINITY,-INFINITY}};
    float lrun[2][2] = {{0.f,0.f},{0.f,0.f}};

    for (int jt = 0; jt < S_LEN / BN; ++jt) {
        __syncthreads();   // previous tile's smem reads complete (covers Q load at jt=0)
        const int k0 = jt * BN;
        for (int i = tid; i < BN * 16; i += THREADS) {
            int row = i >> 4, ch = i & 15;
            size_t gidx = head + (size_t)(k0 + row) * DHEAD + ch * 8;
            float4 t0 = *(const float4*)(K + gidx);
            float4 t1 = *(const float4*)(K + gidx + 4);
            float kf[8] = {t0.x,t0.y,t0.z,t0.w,t1.x,t1.y,t1.z,t1.w};
            uint4 uh, ul; split8(kf, uh, ul);
            uint32_t off = SWZ(row, ch);
            *(uint4*)(sm + SM_KHI + off) = uh;
            *(uint4*)(sm + SM_KLO + off) = ul;
            float4 u0 = *(const float4*)(V + gidx);
            float4 u1 = *(const float4*)(V + gidx + 4);
            float vf[8] = {u0.x,u0.y,u0.z,u0.w,u1.x,u1.y,u1.z,u1.w};
            *(uint4*)(sm + SM_V + off) = pack8(vf);
        }
        __syncthreads();

        // ---- S = Q K^T : 3x fp16 split (hh, lh, hl), 2 m-tiles ----
        float s[2][8][4];
        #pragma unroll
        for (int mt = 0; mt < 2; ++mt)
            #pragma unroll
            for (int i = 0; i < 8; i++) {
                s[mt][i][0]=0.f; s[mt][i][1]=0.f; s[mt][i][2]=0.f; s[mt][i][3]=0.f;
            }

        #pragma unroll 1
        for (int kk = 0; kk < 8; ++kk) {
            const uint32_t offA = ((chA0 + 2 * kk) ^ rl) << 4;
            uint32_t aH[2][4], aL[2][4];
            ldsm4(aH[0], qA_h0 + offA);
            ldsm4(aL[0], qA_l0 + offA);
            ldsm4(aH[1], qA_h0 + 16 * 256u + offA);
            ldsm4(aL[1], qA_l0 + 16 * 256u + offA);
            const uint32_t offB = ((chB0 + 2 * kk) ^ rl) << 4;
            uint32_t bhf[16], blf[16];
            #pragma unroll
            for (int q8 = 0; q8 < 4; ++q8)
                ldsm4(&bhf[q8 * 4], kB_h + (uint32_t)q8 * 4096u + offB);
            #pragma unroll
            for (int q8 = 0; q8 < 4; ++q8)
                ldsm4(&blf[q8 * 4], kB_l + (uint32_t)q8 * 4096u + offB);
            // pass hh: 16 independent accumulators
            #pragma unroll
            for (int mt = 0; mt < 2; ++mt)
                #pragma unroll
                for (int ng = 0; ng < 8; ++ng) mma_f16(s[mt][ng], aH[mt], &bhf[ng * 2]);
            #pragma unroll
            for (int mt = 0; mt < 2; ++mt)
                #pragma unroll
                for (int ng = 0; ng < 8; ++ng) mma_f16(s[mt][ng], aL[mt], &bhf[ng * 2]);
            #pragma unroll
            for (int mt = 0; mt < 2; ++mt)
                #pragma unroll
                for (int ng = 0; ng < 8; ++ng) mma_f16(s[mt][ng], aH[mt], &blf[ng * 2]);
        }

        // ---- online softmax per m-tile (base-2 domain; scale folded into Q) ----
        float alpha[2][2];
        #pragma unroll
        for (int mt = 0; mt < 2; ++mt) {
            float mx0 = -INFINITY, mx1 = -INFINITY;
            #pragma unroll
            for (int ng = 0; ng < 8; ++ng) {
                mx0 = fmaxf(mx0, fmaxf(s[mt][ng][0], s[mt][ng][1]));
                mx1 = fmaxf(mx1, fmaxf(s[mt][ng][2], s[mt][ng][3]));
            }
            mx0 = fmaxf(mx0, __shfl_xor_sync(0xffffffffu, mx0, 1));
            mx0 = fmaxf(mx0, __shfl_xor_sync(0xffffffffu, mx0, 2));
            mx1 = fmaxf(mx1, __shfl_xor_sync(0xffffffffu, mx1, 1));
            mx1 = fmaxf(mx1, __shfl_xor_sync(0xffffffffu, mx1, 2));

            float m0n = fmaxf(mrun[mt][0], mx0), m1n = fmaxf(mrun[mt][1], mx1);
            float al0 = ex2f(mrun[mt][0] - m0n), al1 = ex2f(mrun[mt][1] - m1n);
            float sum0 = 0.f, sum1 = 0.f;
            #pragma unroll
            for (int ng = 0; ng < 8; ++ng) {
                s[mt][ng][0] = ex2f(s[mt][ng][0] - m0n);
                s[mt][ng][1] = ex2f(s[mt][ng][1] - m0n);
                s[mt][ng][2] = ex2f(s[mt][ng][2] - m1n);
                s[mt][ng][3] = ex2f(s[mt][ng][3] - m1n);
                sum0 += s[mt][ng][0] + s[mt][ng][1];
                sum1 += s[mt][ng][2] + s[mt][ng][3];
            }
            sum0 += __shfl_xor_sync(0xffffffffu, sum0, 1);
            sum0 += __shfl_xor_sync(0xffffffffu, sum0, 2);
            sum1 += __shfl_xor_sync(0xffffffffu, sum1, 1);
            sum1 += __shfl_xor_sync(0xffffffffu, sum1, 2);
            lrun[mt][0] = lrun[mt][0] * al0 + sum0;
            lrun[mt][1] = lrun[mt][1] * al1 + sum1;
            mrun[mt][0] = m0n; mrun[mt][1] = m1n;
            alpha[mt][0] = al0; alpha[mt][1] = al1;
            #pragma unroll
            for (int nf = 0; nf < 16; ++nf) {
                o[mt][nf][0] *= al0; o[mt][nf][1] *= al0;
                o[mt][nf][2] *= al1; o[mt][nf][3] *= al1;
            }
        }
        (void)alpha;

        // ---- O += P V : V fragments shared by both m-tiles ----
        #pragma unroll
        for (int k2 = 0; k2 < 4; ++k2) {
            uint32_t pa0[4], pa1[4];
            pa0[0] = pack_h2(s[0][2*k2][0],   s[0][2*k2][1]);
            pa0[1] = pack_h2(s[0][2*k2][2],   s[0][2*k2][3]);
            pa0[2] = pack_h2(s[0][2*k2+1][0], s[0][2*k2+1][1]);
            pa0[3] = pack_h2(s[0][2*k2+1][2], s[0][2*k2+1][3]);
            pa1[0] = pack_h2(s[1][2*k2][0],   s[1][2*k2][1]);
            pa1[1] = pack_h2(s[1][2*k2][2],   s[1][2*k2][3]);
            pa1[2] = pack_h2(s[1][2*k2+1][0], s[1][2*k2+1][1]);
            pa1[3] = pack_h2(s[1][2*k2+1][2], s[1][2*k2+1][3]);
            #pragma unroll
            for (int nfp = 0; nfp < 8; ++nfp) {
                const uint32_t offV = ((chV0 + 2 * nfp) ^ rl) << 4;
                uint32_t bv[4];
                ldsm4t(bv, vB + (uint32_t)k2 * 4096u + offV);
                mma_f16(o[0][2 * nfp],     pa0, bv);
                mma_f16(o[0][2 * nfp + 1], pa0, bv + 2);
                mma_f16(o[1][2 * nfp],     pa1, bv);
                mma_f16(o[1][2 * nfp + 1], pa1, bv + 2);
            }
        }
    }

    // ---- epilogue: normalize and store ----
    #pragma unroll
    for (int mt = 0; mt < 2; ++mt) {
        float inv0 = 1.f / lrun[mt][0], inv1 = 1.f / lrun[mt][1];
        size_t obase = head + (size_t)(q0 + rbase + mt * 16) * DHEAD;
        #pragma unroll
        for (int nf = 0; nf < 16; ++nf) {
            *(float2*)(O + obase + (size_t)(g)     * DHEAD + nf * 8 + c * 2) =
                make_float2(o[mt][nf][0] * inv0, o[mt][nf][1] * inv0);
            *(float2*)(O + obase + (size_t)(g + 8) * DHEAD + nf * 8 + c * 2) =
                make_float2(o[mt][nf][2] * inv1, o[mt][nf][3] * inv1);
        }
    }
}

extern "C" void kernel_launch(void* const* d_in, const int* in_sizes, int n_in,
                              void* d_out, int out_size) {
    const float* q = (const float*)d_in[0];
    const float* k = (const float*)d_in[1];
    const float* v = (const float*)d_in[2];
    float* o = (float*)d_out;

    cudaFuncSetAttribute(fa_w32_kernel, cudaFuncAttributeMaxDynamicSharedMemorySize, SM_TOT);

    dim3 grid(S_LEN / BM, NHEADS);
    fa_w32_kernel<<<grid, THREADS, SM_TOT>>>(q, k, v, o);
}

// round 8
// speedup vs baseline: 1.2204x; 1.2204x over previous
#include <cuda_runtime.h>
#include <cuda_fp16.h>
#include <cstdint>
#include <math.h>

#define S_LEN   2048
#define DHEAD   128
#define NHEADS  64        // B*H = 4*16
#define BM      256
#define BN      64
#define NT      (S_LEN / BN)     // 32
#define THREADS 512              // 16 warps, 16 Q-rows each

// smem layout (bytes): swizzled 256B rows
#define SM_QHI  0
#define SM_QLO  65536
#define SM_K0H  131072
#define SM_K0L  147456
#define SM_V0   163840
#define SM_K1H  180224
#define SM_K1L  196608
#define SM_V1   212992
#define SM_TOT  229376

// (1/0.32) * log2(e), folded into Q at load
#define SFACT   4.5084219932497354f

// swizzled byte offset: row (256B each), ch = 16B chunk index 0..15
#define SWZ(row, ch) ((uint32_t)(row) * 256u + (uint32_t)((((ch) ^ ((row) & 7)) << 4)))

// pre-converted K/V planes (global scratch, zero-init bss)
static __device__ __half g_khi[NHEADS * S_LEN * DHEAD];
static __device__ __half g_klo[NHEADS * S_LEN * DHEAD];
static __device__ __half g_vh [NHEADS * S_LEN * DHEAD];

static __device__ __forceinline__ float ex2f(float x) {
    float r; asm("ex2.approx.f32 %0, %1;" : "=f"(r) : "f"(x)); return r;
}
static __device__ __forceinline__ uint32_t pack_h2(float a, float b) {
    __half2 h = __floats2half2_rn(a, b);
    return *reinterpret_cast<uint32_t*>(&h);
}
static __device__ __forceinline__ void ldsm4(uint32_t* r, uint32_t a) {
    asm volatile("ldmatrix.sync.aligned.m8n8.x4.shared.b16 {%0,%1,%2,%3}, [%4];"
                 : "=r"(r[0]), "=r"(r[1]), "=r"(r[2]), "=r"(r[3]) : "r"(a));
}
static __device__ __forceinline__ void ldsm4t(uint32_t* r, uint32_t a) {
    asm volatile("ldmatrix.sync.aligned.m8n8.x4.trans.shared.b16 {%0,%1,%2,%3}, [%4];"
                 : "=r"(r[0]), "=r"(r[1]), "=r"(r[2]), "=r"(r[3]) : "r"(a));
}
static __device__ __forceinline__ void mma_f16(float* d, const uint32_t* a, const uint32_t* b) {
    asm volatile(
        "mma.sync.aligned.m16n8k16.row.col.f32.f16.f16.f32 "
        "{%0,%1,%2,%3}, {%4,%5,%6,%7}, {%8,%9}, {%0,%1,%2,%3};\n"
        : "+f"(d[0]), "+f"(d[1]), "+f"(d[2]), "+f"(d[3])
        : "r"(a[0]), "r"(a[1]), "r"(a[2]), "r"(a[3]), "r"(b[0]), "r"(b[1]));
}
static __device__ __forceinline__ void split8(const float* x, uint4& uh, uint4& ul) {
    uint32_t h[4], l[4];
    #pragma unroll
    for (int j = 0; j < 4; ++j) {
        float a = x[2 * j], b = x[2 * j + 1];
        __half ha = __float2half_rn(a), hb = __float2half_rn(b);
        h[j] = pack_h2(__half2float(ha), __half2float(hb));
        l[j] = pack_h2(a - __half2float(ha), b - __half2float(hb));
    }
    uh = make_uint4(h[0], h[1], h[2], h[3]);
    ul = make_uint4(l[0], l[1], l[2], l[3]);
}
static __device__ __forceinline__ uint4 pack8(const float* x) {
    return make_uint4(pack_h2(x[0], x[1]), pack_h2(x[2], x[3]),
                      pack_h2(x[4], x[5]), pack_h2(x[6], x[7]));
}
static __device__ __forceinline__ void cpa16(uint32_t dst, const void* src) {
    asm volatile("cp.async.cg.shared.global [%0], [%1], 16;" :: "r"(dst), "l"(src));
}
static __device__ __forceinline__ void cpa_commit() {
    asm volatile("cp.async.commit_group;" ::: "memory");
}
template <int N>
static __device__ __forceinline__ void cpa_wait() {
    asm volatile("cp.async.wait_group %0;" :: "n"(N) : "memory");
}

// ---- pre-pass: convert K -> hi/lo fp16 planes, V -> fp16 ----
__global__ __launch_bounds__(256)
void conv_kv_kernel(const float* __restrict__ K, const float* __restrict__ V) {
    const int64_t nchunk = (int64_t)NHEADS * S_LEN * (DHEAD / 8);
    int64_t idx = (int64_t)blockIdx.x * blockDim.x + threadIdx.x;
    if (idx >= nchunk) return;
    const float* ks = K + idx * 8;
    const float* vs = V + idx * 8;
    float kf[8], vf[8];
    float4 t0 = *(const float4*)ks;
    float4 t1 = *(const float4*)(ks + 4);
    kf[0]=t0.x; kf[1]=t0.y; kf[2]=t0.z; kf[3]=t0.w;
    kf[4]=t1.x; kf[5]=t1.y; kf[6]=t1.z; kf[7]=t1.w;
    float4 u0 = *(const float4*)vs;
    float4 u1 = *(const float4*)(vs + 4);
    vf[0]=u0.x; vf[1]=u0.y; vf[2]=u0.z; vf[3]=u0.w;
    vf[4]=u1.x; vf[5]=u1.y; vf[6]=u1.z; vf[7]=u1.w;
    uint4 uh, ul; split8(kf, uh, ul);
    *(uint4*)(g_khi + idx * 8) = uh;
    *(uint4*)(g_klo + idx * 8) = ul;
    *(uint4*)(g_vh  + idx * 8) = pack8(vf);
}

__global__ __launch_bounds__(THREADS, 1)
void fa_db_kernel(const float* __restrict__ Q, float* __restrict__ O) {
    extern __shared__ __align__(16) char sm[];
    const uint32_t smb = (uint32_t)__cvta_generic_to_shared(sm);

    const int tid  = threadIdx.x;
    const int warp = tid >> 5;
    const int lane = tid & 31;
    const int g    = lane >> 2;
    const int c    = lane & 3;
    const uint32_t rl = lane & 7;

    const int bh = blockIdx.y;
    const int q0 = blockIdx.x * BM;
    const size_t head = (size_t)bh * S_LEN * DHEAD;
    const int rbase = warp * 16;

    const __half* khs = g_khi + head;
    const __half* kls = g_klo + head;
    const __half* vhs = g_vh  + head;

    // ---- load Q tile: scale, split hi/lo fp16, swizzled store ----
    for (int i = tid; i < BM * 16; i += THREADS) {
        int row = i >> 4, ch = i & 15;
        const float* src = Q + head + (size_t)(q0 + row) * DHEAD + ch * 8;
        float4 f0 = *(const float4*)src;
        float4 f1 = *(const float4*)(src + 4);
        float f[8] = {f0.x*SFACT, f0.y*SFACT, f0.z*SFACT, f0.w*SFACT,
                      f1.x*SFACT, f1.y*SFACT, f1.z*SFACT, f1.w*SFACT};
        uint4 uh, ul; split8(f, uh, ul);
        uint32_t off = SWZ(row, ch);
        *(uint4*)(sm + SM_QHI + off) = uh;
        *(uint4*)(sm + SM_QLO + off) = ul;
    }

    // ---- async fill of K/V buffers (6 cp.async.16B per thread per tile) ----
    auto fill = [&](int jt, int buf) {
        const int k0 = jt * BN;
        const uint32_t dkh = smb + (buf ? SM_K1H : SM_K0H);
        const uint32_t dkl = smb + (buf ? SM_K1L : SM_K0L);
        const uint32_t dv  = smb + (buf ? SM_V1  : SM_V0);
        #pragma unroll
        for (int it = 0; it < 2; ++it) {
            int i = tid + it * THREADS;          // 0..1023
            int row = i >> 4, ch = i & 15;
            uint32_t off = SWZ(row, ch);
            size_t sidx = (size_t)(k0 + row) * DHEAD + ch * 8;
            cpa16(dkh + off, khs + sidx);
            cpa16(dkl + off, kls + sidx);
            cpa16(dv  + off, vhs + sidx);
        }
        cpa_commit();
    };

    fill(0, 0);

    // ---- per-lane fragment row offsets ----
    const uint32_t qrow = (uint32_t)(rbase + (lane & 15)) * 256u;
    const uint32_t chA0 = lane >> 4;
    const uint32_t krow = (uint32_t)((lane & 7) + ((lane >> 4) << 3)) * 256u;
    const uint32_t chB0 = (lane >> 3) & 1;
    const uint32_t vrow = (uint32_t)((lane & 7) + (((lane >> 3) & 1) << 3)) * 256u;
    const uint32_t chV0 = lane >> 4;

    const uint32_t qA_h = smb + SM_QHI + qrow;
    const uint32_t qA_l = smb + SM_QLO + qrow;

    float o[16][4];
    #pragma unroll
    for (int i = 0; i < 16; i++) { o[i][0]=0.f; o[i][1]=0.f; o[i][2]=0.f; o[i][3]=0.f; }
    float m0 = -INFINITY, m1 = -INFINITY, l0 = 0.f, l1 = 0.f;

    for (int jt = 0; jt < NT; ++jt) {
        __syncthreads();   // prior compute done (and Q stores at jt=0) before refill/consume
        if (jt + 1 < NT) { fill(jt + 1, (jt + 1) & 1); cpa_wait<1>(); }
        else             { cpa_wait<0>(); }
        __syncthreads();   // buffer jt visible to all

        const int buf = jt & 1;
        const uint32_t kB_h = smb + (buf ? SM_K1H : SM_K0H) + krow;
        const uint32_t kB_l = smb + (buf ? SM_K1L : SM_K0L) + krow;
        const uint32_t vB   = smb + (buf ? SM_V1  : SM_V0)  + vrow;

        // ---- S = Q K^T : 3x fp16 split (hh, lh, hl) ----
        float s[8][4];
        #pragma unroll
        for (int i = 0; i < 8; i++) { s[i][0]=0.f; s[i][1]=0.f; s[i][2]=0.f; s[i][3]=0.f; }

        #pragma unroll 2
        for (int kk = 0; kk < 8; ++kk) {
            const uint32_t offA = ((chA0 + 2 * kk) ^ rl) << 4;
            uint32_t aH[4], aL[4];
            ldsm4(aH, qA_h + offA);
            ldsm4(aL, qA_l + offA);
            const uint32_t offB = ((chB0 + 2 * kk) ^ rl) << 4;
            #pragma unroll
            for (int hfl = 0; hfl < 2; ++hfl) {
                const uint32_t bbase = (uint32_t)hfl * 8192u + offB;
                uint32_t bhf[8], blf[8];
                ldsm4(&bhf[0], kB_h + bbase);
                ldsm4(&bhf[4], kB_h + bbase + 4096u);
                ldsm4(&blf[0], kB_l + bbase);
                ldsm4(&blf[4], kB_l + bbase + 4096u);
                float (*sp)[4] = &s[hfl * 4];
                #pragma unroll
                for (int j = 0; j < 4; ++j) mma_f16(sp[j], aH, &bhf[j * 2]);
                #pragma unroll
                for (int j = 0; j < 4; ++j) mma_f16(sp[j], aL, &bhf[j * 2]);
                #pragma unroll
                for (int j = 0; j < 4; ++j) mma_f16(sp[j], aH, &blf[j * 2]);
            }
        }

        // ---- online softmax (base-2 domain; scale folded into Q) ----
        float mx0 = -INFINITY, mx1 = -INFINITY;
        #pragma unroll
        for (int ng = 0; ng < 8; ++ng) {
            mx0 = fmaxf(mx0, fmaxf(s[ng][0], s[ng][1]));
            mx1 = fmaxf(mx1, fmaxf(s[ng][2], s[ng][3]));
        }
        mx0 = fmaxf(mx0, __shfl_xor_sync(0xffffffffu, mx0, 1));
        mx0 = fmaxf(mx0, __shfl_xor_sync(0xffffffffu, mx0, 2));
        mx1 = fmaxf(mx1, __shfl_xor_sync(0xffffffffu, mx1, 1));
        mx1 = fmaxf(mx1, __shfl_xor_sync(0xffffffffu, mx1, 2));

        float m0n = fmaxf(m0, mx0), m1n = fmaxf(m1, mx1);
        float al0 = ex2f(m0 - m0n), al1 = ex2f(m1 - m1n);
        float sum0 = 0.f, sum1 = 0.f;
        #pragma unroll
        for (int ng = 0; ng < 8; ++ng) {
            s[ng][0] = ex2f(s[ng][0] - m0n);
            s[ng][1] = ex2f(s[ng][1] - m0n);
            s[ng][2] = ex2f(s[ng][2] - m1n);
            s[ng][3] = ex2f(s[ng][3] - m1n);
            sum0 += s[ng][0] + s[ng][1];
            sum1 += s[ng][2] + s[ng][3];
        }
        sum0 += __shfl_xor_sync(0xffffffffu, sum0, 1);
        sum0 += __shfl_xor_sync(0xffffffffu, sum0, 2);
        sum1 += __shfl_xor_sync(0xffffffffu, sum1, 1);
        sum1 += __shfl_xor_sync(0xffffffffu, sum1, 2);
        l0 = l0 * al0 + sum0;
        l1 = l1 * al1 + sum1;
        m0 = m0n; m1 = m1n;
        #pragma unroll
        for (int nf = 0; nf < 16; ++nf) {
            o[nf][0] *= al0; o[nf][1] *= al0; o[nf][2] *= al1; o[nf][3] *= al1;
        }

        // ---- O += P V : P accum frag -> fp16 A frag directly in registers ----
        #pragma unroll
        for (int k2 = 0; k2 < 4; ++k2) {
            uint32_t pa[4];
            pa[0] = pack_h2(s[2 * k2][0],     s[2 * k2][1]);
            pa[1] = pack_h2(s[2 * k2][2],     s[2 * k2][3]);
            pa[2] = pack_h2(s[2 * k2 + 1][0], s[2 * k2 + 1][1]);
            pa[3] = pack_h2(s[2 * k2 + 1][2], s[2 * k2 + 1][3]);
            #pragma unroll
            for (int nfp = 0; nfp < 8; ++nfp) {
                const uint32_t offV = ((chV0 + 2 * nfp) ^ rl) << 4;
                uint32_t bv[4];
                ldsm4t(bv, vB + (uint32_t)k2 * 4096u + offV);
                mma_f16(o[2 * nfp],     pa, bv);
                mma_f16(o[2 * nfp + 1], pa, bv + 2);
            }
        }
    }

    // ---- epilogue: normalize and store ----
    float inv0 = 1.f / l0, inv1 = 1.f / l1;
    size_t obase = head + (size_t)(q0 + rbase) * DHEAD;
    #pragma unroll
    for (int nf = 0; nf < 16; ++nf) {
        *(float2*)(O + obase + (size_t)(g)     * DHEAD + nf * 8 + c * 2) =
            make_float2(o[nf][0] * inv0, o[nf][1] * inv0);
        *(float2*)(O + obase + (size_t)(g + 8) * DHEAD + nf * 8 + c * 2) =
            make_float2(o[nf][2] * inv1, o[nf][3] * inv1);
    }
}

extern "C" void kernel_launch(void* const* d_in, const int* in_sizes, int n_in,
                              void* d_out, int out_size) {
    const float* q = (const float*)d_in[0];
    const float* k = (const float*)d_in[1];
    const float* v = (const float*)d_in[2];
    float* o = (float*)d_out;

    // pre-pass: convert K/V once per launch
    const int64_t nchunk = (int64_t)NHEADS * S_LEN * (DHEAD / 8);
    conv_kv_kernel<<<(int)((nchunk + 255) / 256), 256>>>(k, v);

    cudaFuncSetAttribute(fa_db_kernel, cudaFuncAttributeMaxDynamicSharedMemorySize, SM_TOT);
    dim3 grid(S_LEN / BM, NHEADS);
    fa_db_kernel<<<grid, THREADS, SM_TOT>>>(q, o);
}